// round 12
// baseline (speedup 1.0000x reference)
#include <cuda_runtime.h>
#include <math.h>

#define TB      32768      // T*B images
#define T_STEPS 64
#define NB      5120       // LSTM batch = B*10
#define HID     112
#define G4      448        // 4*HID
#define RROWS   40         // LSTM rows per block
#define LBLK    128        // NB / RROWS
#define LTHR    256        // 8 warps, 5 rows per warp

// ---------------- scratch (device globals; no runtime allocation) ----------------
__device__ float g_f1[(size_t)TB * 1440];              // (TB,10,12,12)
__device__ float g_f2[(size_t)TB * 720];               // (TB,20,6,6)
__device__ float g_x [(size_t)T_STEPS * NB * 36];      // (T,NB,36)
__device__ float g_G [(size_t)T_STEPS * NB * G4];      // (T,NB,448) NORMAL layout n = gate*112+hc

// ---------------- f32x2 packed-math helpers ----------------
#define PACK2(d, lo, hi) asm("mov.b64 %0, {%1, %2};" : "=l"(d) : "f"(lo), "f"(hi))
#define UNPACK2(lo, hi, v) asm("mov.b64 {%0, %1}, %2;" : "=f"(lo), "=f"(hi) : "l"(v))
#define FFMA2(d, a, b, c) asm("fma.rn.f32x2 %0, %1, %2, %3;" : "=l"(d) : "l"(a), "l"(b), "l"(c))

__device__ __forceinline__ float sigm_f(float x) { return 1.f / (1.f + __expf(-x)); }
__device__ __forceinline__ float tanh_a(float x) {
    float y;
    asm("tanh.approx.f32 %0, %1;" : "=f"(y) : "f"(x));
    return y;
}

// ---------------- conv1: (1,24,24) -> conv3x3 SAME + relu + pool2 -> (10,12,12) ----------------
// (R1 verbatim — measured passing)
__global__ __launch_bounds__(288) void k_conv1(const float* __restrict__ imgs,
                                               const float* __restrict__ w1,
                                               const float* __restrict__ b1) {
    __shared__ float s_img[2][26 * 26];
    __shared__ float s_w[90];
    __shared__ float s_b[10];
    int tid = threadIdx.x;
    int i0  = blockIdx.x * 2;
    for (int idx = tid; idx < 2 * 676; idx += 288) ((float*)s_img)[idx] = 0.f;
    if (tid < 90) s_w[tid] = w1[tid];
    if (tid < 10) s_b[tid] = b1[tid];
    __syncthreads();
    for (int idx = tid; idx < 2 * 576; idx += 288) {
        int li = idx / 576, r = idx % 576;
        int y = r / 24, x = r % 24;
        s_img[li][(y + 1) * 26 + (x + 1)] = imgs[(size_t)(i0 + li) * 576 + r];
    }
    __syncthreads();
    int li  = tid / 144;
    int pos = tid % 144;
    int py = pos / 12, px = pos % 12;
    float p[4][4];
#pragma unroll
    for (int a = 0; a < 4; a++)
#pragma unroll
        for (int b = 0; b < 4; b++)
            p[a][b] = s_img[li][(2 * py + a) * 26 + (2 * px + b)];
    float* out = g_f1 + (size_t)(i0 + li) * 1440 + pos;
#pragma unroll
    for (int c = 0; c < 10; c++) {
        float bb = s_b[c];
        float a00 = bb, a01 = bb, a10 = bb, a11 = bb;
#pragma unroll
        for (int ky = 0; ky < 3; ky++)
#pragma unroll
            for (int kx = 0; kx < 3; kx++) {
                float w = s_w[c * 9 + ky * 3 + kx];
                a00 += p[ky][kx] * w;
                a01 += p[ky][kx + 1] * w;
                a10 += p[ky + 1][kx] * w;
                a11 += p[ky + 1][kx + 1] * w;
            }
        out[c * 144] = fmaxf(fmaxf(fmaxf(a00, a01), fmaxf(a10, a11)), 0.f);
    }
}

// ---------------- conv2: (10,12,12) -> (20,6,6), f32x2 packed, NO reg cap ----------------
// correctness verified in R4 (passed); cap removal is perf-only
__global__ __launch_bounds__(288) void k_conv2(const float* __restrict__ w2,
                                               const float* __restrict__ b2) {
    __shared__ float  s_in[4][10][14 * 14];
    __shared__ float2 s_wd[1800];          // duplicated weights (w,w)
    __shared__ float  s_b[20];
    int tid = threadIdx.x;
    int i0  = blockIdx.x * 4;
    for (int idx = tid; idx < 4 * 10 * 196; idx += 288) ((float*)s_in)[idx] = 0.f;
    for (int idx = tid; idx < 1800; idx += 288) {
        float w = w2[idx];
        s_wd[idx] = make_float2(w, w);
    }
    if (tid < 20) s_b[tid] = b2[tid];
    __syncthreads();
    for (int idx = tid; idx < 4 * 1440; idx += 288) {
        int li = idx / 1440, r = idx % 1440;
        int c = r / 144, rr = r % 144;
        int y = rr / 12, x = rr % 12;
        s_in[li][c][(y + 1) * 14 + (x + 1)] = g_f1[(size_t)(i0 + li) * 1440 + r];
    }
    __syncthreads();
    int li  = tid / 72;
    int rem = tid % 72;
    int grp = rem / 36;
    int pos = rem % 36;
    int py = pos / 6, px = pos % 6;
    unsigned long long A0[10], A1[10];   // A0 = (a00,a01), A1 = (a10,a11)
#pragma unroll
    for (int c = 0; c < 10; c++) {
        float bb = s_b[grp * 10 + c];
        PACK2(A0[c], bb, bb);
        A1[c] = A0[c];
    }
    const unsigned long long* wd = (const unsigned long long*)s_wd;
    for (int ic = 0; ic < 10; ic++) {
        float p[4][4];
#pragma unroll
        for (int a = 0; a < 4; a++)
#pragma unroll
            for (int b = 0; b < 4; b++)
                p[a][b] = s_in[li][ic][(2 * py + a) * 14 + (2 * px + b)];
        unsigned long long pp[4][3];
#pragma unroll
        for (int a = 0; a < 4; a++)
#pragma unroll
            for (int b = 0; b < 3; b++)
                PACK2(pp[a][b], p[a][b], p[a][b + 1]);
#pragma unroll
        for (int c = 0; c < 10; c++) {
            const unsigned long long* w = &wd[((grp * 10 + c) * 10 + ic) * 9];
#pragma unroll
            for (int ky = 0; ky < 3; ky++)
#pragma unroll
                for (int kx = 0; kx < 3; kx++) {
                    unsigned long long wv = w[ky * 3 + kx];
                    FFMA2(A0[c], pp[ky][kx],     wv, A0[c]);
                    FFMA2(A1[c], pp[ky + 1][kx], wv, A1[c]);
                }
        }
    }
    float* out = g_f2 + (size_t)(i0 + li) * 720 + pos;
#pragma unroll
    for (int c = 0; c < 10; c++) {
        float a00, a01, a10, a11;
        UNPACK2(a00, a01, A0[c]);
        UNPACK2(a10, a11, A1[c]);
        float v = fmaxf(fmaxf(fmaxf(a00, a01), fmaxf(a10, a11)), 0.f);
        out[(grp * 10 + c) * 36] = v;
    }
}

// ---------------- conv3: (20,6,6) -> (40,3,3), 8 images/block, f32x2 packed, NO reg cap ----------------
// correctness verified in R4 (passed); cap removal is perf-only
__global__ __launch_bounds__(288) void k_conv3(const float* __restrict__ w3,
                                               const float* __restrict__ b3) {
    extern __shared__ float sm3[];
    float*  s_in = sm3;                          // [8][20][64] zero-padded 8x8
    float2* s_wd = (float2*)(sm3 + 8 * 20 * 64); // 7200 duplicated weights
    float*  s_b  = (float*)(s_wd + 7200);        // 40
    int tid = threadIdx.x;
    int i0  = blockIdx.x * 8;
    for (int idx = tid; idx < 8 * 20 * 64; idx += 288) s_in[idx] = 0.f;
    for (int idx = tid; idx < 7200; idx += 288) {
        float w = w3[idx];
        s_wd[idx] = make_float2(w, w);
    }
    if (tid < 40) s_b[tid] = b3[tid];
    __syncthreads();
    for (int idx = tid; idx < 8 * 720; idx += 288) {
        int li = idx / 720, r = idx % 720;
        int c = r / 36, rr = r % 36;
        int y = rr / 6, x = rr % 6;
        s_in[(li * 20 + c) * 64 + (y + 1) * 8 + (x + 1)] = g_f2[(size_t)(i0 + li) * 720 + r];
    }
    __syncthreads();
    int li  = tid / 36;
    int rem = tid % 36;
    int grp = rem / 9;
    int pos = rem % 9;
    int py = pos / 3, px = pos % 3;
    unsigned long long A0[10], A1[10];
#pragma unroll
    for (int c = 0; c < 10; c++) {
        float bb = s_b[grp * 10 + c];
        PACK2(A0[c], bb, bb);
        A1[c] = A0[c];
    }
    const unsigned long long* wd = (const unsigned long long*)s_wd;
    for (int ic = 0; ic < 20; ic++) {
        const float* sp = &s_in[(li * 20 + ic) * 64 + (2 * py) * 8 + 2 * px];
        float p[4][4];
#pragma unroll
        for (int a = 0; a < 4; a++)
#pragma unroll
            for (int b = 0; b < 4; b++)
                p[a][b] = sp[a * 8 + b];
        unsigned long long pp[4][3];
#pragma unroll
        for (int a = 0; a < 4; a++)
#pragma unroll
            for (int b = 0; b < 3; b++)
                PACK2(pp[a][b], p[a][b], p[a][b + 1]);
#pragma unroll
        for (int c = 0; c < 10; c++) {
            const unsigned long long* w = &wd[((grp * 10 + c) * 20 + ic) * 9];
#pragma unroll
            for (int ky = 0; ky < 3; ky++)
#pragma unroll
                for (int kx = 0; kx < 3; kx++) {
                    unsigned long long wv = w[ky * 3 + kx];
                    FFMA2(A0[c], pp[ky][kx],     wv, A0[c]);
                    FFMA2(A1[c], pp[ky + 1][kx], wv, A1[c]);
                }
        }
    }
    int i = i0 + li;
    int t = i >> 9;      // /512
    int b = i & 511;
#pragma unroll
    for (int c0 = 0; c0 < 10; c0++) {
        int c = grp * 10 + c0;
        int e = c * 9 + pos;        // flatten (40,3,3)
        int r = e / 36, j = e % 36; // view(-1,36)
        float a00, a01, a10, a11;
        UNPACK2(a00, a01, A0[c0]);
        UNPACK2(a10, a11, A1[c0]);
        float v = fmaxf(fmaxf(fmaxf(a00, a01), fmaxf(a10, a11)), 0.f);
        g_x[((size_t)t * NB + b * 10 + r) * 36 + j] = v;
    }
}

// ---------------- xW precompute (R1/R9 verbatim — coalesced float4 stores, NORMAL layout) ----------------
__global__ __launch_bounds__(256) void k_xw(const float* __restrict__ w_ih,
                                            const float* __restrict__ b_ih,
                                            const float* __restrict__ b_hh) {
    __shared__ float A_s[36 * 132];
    __shared__ float B_s[36 * 68];
    int tid = threadIdx.x;
    long m0 = (long)blockIdx.x * 128;
    int  n0 = blockIdx.y * 64;
    for (int idx = tid; idx < 128 * 36; idx += 256) {
        int mm = idx / 36, k = idx % 36;
        A_s[k * 132 + mm] = g_x[m0 * 36 + idx];
    }
    for (int idx = tid; idx < 64 * 36; idx += 256) {
        int nn = idx / 36, k = idx % 36;
        B_s[k * 68 + nn] = w_ih[(n0 + nn) * 36 + k];
    }
    __syncthreads();
    int cg = tid & 15, rg = tid >> 4;
    float acc[8][4];
#pragma unroll
    for (int i = 0; i < 8; i++)
#pragma unroll
        for (int j = 0; j < 4; j++) acc[i][j] = 0.f;
#pragma unroll
    for (int k = 0; k < 36; k++) {
        float4 a0 = *(const float4*)&A_s[k * 132 + rg * 8];
        float4 a1 = *(const float4*)&A_s[k * 132 + rg * 8 + 4];
        float4 bv = *(const float4*)&B_s[k * 68 + cg * 4];
        float a[8] = {a0.x, a0.y, a0.z, a0.w, a1.x, a1.y, a1.z, a1.w};
        float b[4] = {bv.x, bv.y, bv.z, bv.w};
#pragma unroll
        for (int i = 0; i < 8; i++)
#pragma unroll
            for (int j = 0; j < 4; j++) acc[i][j] += a[i] * b[j];
    }
    float bias[4];
#pragma unroll
    for (int j = 0; j < 4; j++) {
        int col = n0 + cg * 4 + j;
        bias[j] = b_ih[col] + b_hh[col];
    }
#pragma unroll
    for (int i = 0; i < 8; i++) {
        long row = m0 + rg * 8 + i;
        float4 o = make_float4(acc[i][0] + bias[0], acc[i][1] + bias[1],
                               acc[i][2] + bias[2], acc[i][3] + bias[3]);
        *(float4*)&g_G[row * 448 + n0 + cg * 4] = o;
    }
}

// ---------------- LSTM: block-local recurrence (R9 verbatim — measured in 3704us total) ----------------
// block = 40 rows x all 448 gate cols x 64 steps. 256 threads (8 warps x 5 rows).
__global__ __launch_bounds__(LTHR) void k_lstm(const float* __restrict__ w_hh,
                                               const float* __restrict__ h0,
                                               const float* __restrict__ c0,
                                               const float* __restrict__ wf,
                                               const float* __restrict__ bf,
                                               float* __restrict__ out) {
    extern __shared__ float sm[];
    float* wT  = sm;               // [112][448]
    float* h_s = sm + 112 * 448;   // [112][40]  (k-major, stride 40)
    int tid  = threadIdx.x;
    int warp = tid >> 5, lane = tid & 31;
    int r0   = warp * 5;           // 8 warps x 5 rows = 40
    int row0 = blockIdx.x * RROWS;

    // build permuted wT: wT[k][m] = w_hh[n(m)][k], n(m) = (m&3)*112 + (m>>2)
    for (int idx = tid; idx < 448 * 28; idx += LTHR) {
        int n = idx / 28, k4 = (idx % 28) * 4;
        float4 v = *(const float4*)&w_hh[n * 112 + k4];
        int m = ((n % 112) << 2) | (n / 112);
        wT[(k4 + 0) * 448 + m] = v.x;
        wT[(k4 + 1) * 448 + m] = v.y;
        wT[(k4 + 2) * 448 + m] = v.z;
        wT[(k4 + 3) * 448 + m] = v.w;
    }
    // init h: all rows = h0
    for (int idx = tid; idx < 112 * RROWS; idx += LTHR)
        h_s[idx] = h0[idx / RROWS];

    bool evenl = (lane & 1) == 0;
    int  hpair = lane >> 1;
    // cell state: BOTH lanes of a pair keep c for all 7 jj (redundant, removes divergence)
    float c_reg[5][7];
#pragma unroll
    for (int jj = 0; jj < 7; jj++) {
        float cv = c0[hpair + 16 * jj];
#pragma unroll
        for (int r = 0; r < 5; r++) c_reg[r][jj] = cv;
    }
    __syncthreads();

    const float* Gb = g_G + (size_t)row0 * 448;
    int nlo = (evenl ? 0 : 224);   // unpermuted gate-block base for this lane's packed pair
    for (int t = 0; t < T_STEPS; t++) {
        const float* Gt = Gb + (size_t)t * NB * 448;
        unsigned long long acc[5][7];
#pragma unroll
        for (int r = 0; r < 5; r++) {
            const float* gr = Gt + (size_t)(r0 + r) * 448;
#pragma unroll
            for (int jj = 0; jj < 7; jj++) {
                int hc = hpair + 16 * jj;
                float lo = __ldg(&gr[nlo + hc]);          // gate i (even) / g (odd)
                float hi = __ldg(&gr[nlo + 112 + hc]);    // gate f (even) / o (odd)
                PACK2(acc[r][jj], lo, hi);
            }
        }
        // GEMM: acc += h @ wT
#pragma unroll 2
        for (int k = 0; k < 112; k++) {
            unsigned long long ad[5];
#pragma unroll
            for (int r = 0; r < 5; r++) {
                float av = h_s[k * RROWS + r0 + r];
                PACK2(ad[r], av, av);
            }
            const unsigned long long* wp =
                (const unsigned long long*)(wT + k * 448 + 2 * lane);
#pragma unroll
            for (int jj = 0; jj < 7; jj++) {
                unsigned long long bv = wp[32 * jj];
#pragma unroll
                for (int r = 0; r < 5; r++) FFMA2(acc[r][jj], ad[r], bv, acc[r][jj]);
            }
        }
        __syncthreads();   // all GEMM reads of h_s done before overwrite

        // epilogue: exchange with pair lane; both lanes compute the shared cell (no divergence)
#pragma unroll
        for (int r = 0; r < 5; r++) {
#pragma unroll
            for (int jj = 0; jj < 7; jj++) {
                unsigned long long other = __shfl_xor_sync(0xffffffffu, acc[r][jj], 1);
                float x0, x1, y0, y1;
                UNPACK2(x0, x1, acc[r][jj]);
                UNPACK2(y0, y1, other);
                float gi = evenl ? x0 : y0;
                float gf = evenl ? x1 : y1;
                float gg = evenl ? y0 : x0;
                float go = evenl ? y1 : x1;
                float is = sigm_f(gi), fs = sigm_f(gf), os = sigm_f(go);
                float gt = tanh_a(gg);
                float cn = fs * c_reg[r][jj] + is * gt;
                c_reg[r][jj] = cn;
                if (evenl) {
                    int hc = hpair + 16 * jj;
                    h_s[hc * RROWS + r0 + r] = os * tanh_a(cn);
                }
            }
        }
        __syncthreads();
    }

    // head: softmax(h @ wf^T + bf) for this block's 40 rows (reuse wT region as scratch)
    float* lg = wT;   // [40][3]
    if (tid < 120) {
        int r = tid / 3, o = tid % 3;
        float s = bf[o];
        const float* wfo = wf + o * 112;
        for (int k = 0; k < 112; k++) s += h_s[k * RROWS + r] * wfo[k];
        lg[r * 3 + o] = s;
    }
    __syncthreads();
    if (tid < RROWS) {
        float l0 = lg[tid * 3], l1 = lg[tid * 3 + 1], l2 = lg[tid * 3 + 2];
        float mx = fmaxf(l0, fmaxf(l1, l2));
        float e0 = __expf(l0 - mx), e1 = __expf(l1 - mx), e2 = __expf(l2 - mx);
        float s = e0 + e1 + e2;
        int m = row0 + tid;
        out[m * 3 + 0] = e0 / s;
        out[m * 3 + 1] = e1 / s;
        out[m * 3 + 2] = e2 / s;
    }
}

// ---------------- launch ----------------
extern "C" void kernel_launch(void* const* d_in, const int* in_sizes, int n_in,
                              void* d_out, int out_size) {
    const float* imgs = (const float*)d_in[0];
    const float* w1   = (const float*)d_in[1];
    const float* b1   = (const float*)d_in[2];
    const float* w2   = (const float*)d_in[3];
    const float* b2   = (const float*)d_in[4];
    const float* w3   = (const float*)d_in[5];
    const float* b3   = (const float*)d_in[6];
    const float* w_ih = (const float*)d_in[7];
    const float* w_hh = (const float*)d_in[8];
    const float* b_ih = (const float*)d_in[9];
    const float* b_hh = (const float*)d_in[10];
    const float* wf   = (const float*)d_in[11];
    const float* bf   = (const float*)d_in[12];
    const float* h0   = (const float*)d_in[13];
    const float* c0   = (const float*)d_in[14];

    size_t conv3_smem = (size_t)(8 * 20 * 64) * 4 + 7200 * 8 + 40 * 4;        // 98,720 B
    size_t lstm_smem  = (size_t)(112 * 448 + 112 * RROWS) * sizeof(float);    // 218,624 B
    cudaFuncSetAttribute(k_conv3, cudaFuncAttributeMaxDynamicSharedMemorySize, (int)(100 * 1024));
    cudaFuncSetAttribute(k_lstm,  cudaFuncAttributeMaxDynamicSharedMemorySize, (int)(220 * 1024));

    k_conv1<<<TB / 2, 288>>>(imgs, w1, b1);
    k_conv2<<<TB / 4, 288>>>(w2, b2);
    k_conv3<<<TB / 8, 288, conv3_smem>>>(w3, b3);
    dim3 gx(2560, 7);
    k_xw<<<gx, 256>>>(w_ih, b_ih, b_hh);
    k_lstm<<<LBLK, LTHR, lstm_smem>>>(w_hh, h0, c0, wf, bf, (float*)d_out);
}

// round 13
// speedup vs baseline: 1.4640x; 1.4640x over previous
#include <cuda_runtime.h>
#include <math.h>

#define TB      32768      // T*B images
#define T_STEPS 64
#define NB      5120       // LSTM batch = B*10
#define HID     112
#define G4      448        // 4*HID
#define RROWS   40         // LSTM rows per block
#define LBLK    128        // NB / RROWS
#define LTHR    256        // 8 warps, 5 rows per warp

// ---------------- scratch (device globals; no runtime allocation) ----------------
__device__ float g_f1[(size_t)TB * 1440];              // (TB,10,12,12)
__device__ float g_f2[(size_t)TB * 720];               // (TB,20,6,6)
__device__ float g_x [(size_t)T_STEPS * NB * 36];      // (T,NB,36)
__device__ float g_G [(size_t)T_STEPS * NB * G4];      // (T,NB,448) NORMAL layout n = gate*112+hc

// ---------------- f32x2 packed-math helpers (LSTM only) ----------------
#define PACK2(d, lo, hi) asm("mov.b64 %0, {%1, %2};" : "=l"(d) : "f"(lo), "f"(hi))
#define UNPACK2(lo, hi, v) asm("mov.b64 {%0, %1}, %2;" : "=f"(lo), "=f"(hi) : "l"(v))
#define FFMA2(d, a, b, c) asm("fma.rn.f32x2 %0, %1, %2, %3;" : "=l"(d) : "l"(a), "l"(b), "l"(c))

__device__ __forceinline__ float tanh_a(float x) {
    float y;
    asm("tanh.approx.f32 %0, %1;" : "=f"(y) : "f"(x));
    return y;
}
// sigmoid via tanh: 1 MUFU instead of 2 (EX2 + RCP)
__device__ __forceinline__ float sigm_t(float x) { return 0.5f * tanh_a(0.5f * x) + 0.5f; }

// ---------------- conv1: (1,24,24) -> conv3x3 SAME + relu + pool2 -> (10,12,12) ----------------
// (R1 verbatim — measured passing)
__global__ __launch_bounds__(288) void k_conv1(const float* __restrict__ imgs,
                                               const float* __restrict__ w1,
                                               const float* __restrict__ b1) {
    __shared__ float s_img[2][26 * 26];
    __shared__ float s_w[90];
    __shared__ float s_b[10];
    int tid = threadIdx.x;
    int i0  = blockIdx.x * 2;
    for (int idx = tid; idx < 2 * 676; idx += 288) ((float*)s_img)[idx] = 0.f;
    if (tid < 90) s_w[tid] = w1[tid];
    if (tid < 10) s_b[tid] = b1[tid];
    __syncthreads();
    for (int idx = tid; idx < 2 * 576; idx += 288) {
        int li = idx / 576, r = idx % 576;
        int y = r / 24, x = r % 24;
        s_img[li][(y + 1) * 26 + (x + 1)] = imgs[(size_t)(i0 + li) * 576 + r];
    }
    __syncthreads();
    int li  = tid / 144;
    int pos = tid % 144;
    int py = pos / 12, px = pos % 12;
    float p[4][4];
#pragma unroll
    for (int a = 0; a < 4; a++)
#pragma unroll
        for (int b = 0; b < 4; b++)
            p[a][b] = s_img[li][(2 * py + a) * 26 + (2 * px + b)];
    float* out = g_f1 + (size_t)(i0 + li) * 1440 + pos;
#pragma unroll
    for (int c = 0; c < 10; c++) {
        float bb = s_b[c];
        float a00 = bb, a01 = bb, a10 = bb, a11 = bb;
#pragma unroll
        for (int ky = 0; ky < 3; ky++)
#pragma unroll
            for (int kx = 0; kx < 3; kx++) {
                float w = s_w[c * 9 + ky * 3 + kx];
                a00 += p[ky][kx] * w;
                a01 += p[ky][kx + 1] * w;
                a10 += p[ky + 1][kx] * w;
                a11 += p[ky + 1][kx + 1] * w;
            }
        out[c * 144] = fmaxf(fmaxf(fmaxf(a00, a01), fmaxf(a10, a11)), 0.f);
    }
}

// ---------------- conv2: (10,12,12) -> (20,6,6) (R1 verbatim — measured passing) ----------------
__global__ __launch_bounds__(288) void k_conv2(const float* __restrict__ w2,
                                               const float* __restrict__ b2) {
    __shared__ float s_in[4][10][14 * 14];
    __shared__ float s_w[1800];
    __shared__ float s_b[20];
    int tid = threadIdx.x;
    int i0  = blockIdx.x * 4;
    for (int idx = tid; idx < 4 * 10 * 196; idx += 288) ((float*)s_in)[idx] = 0.f;
    for (int idx = tid; idx < 1800; idx += 288) s_w[idx] = w2[idx];
    if (tid < 20) s_b[tid] = b2[tid];
    __syncthreads();
    for (int idx = tid; idx < 4 * 1440; idx += 288) {
        int li = idx / 1440, r = idx % 1440;
        int c = r / 144, rr = r % 144;
        int y = rr / 12, x = rr % 12;
        s_in[li][c][(y + 1) * 14 + (x + 1)] = g_f1[(size_t)(i0 + li) * 1440 + r];
    }
    __syncthreads();
    int li  = tid / 72;
    int rem = tid % 72;
    int grp = rem / 36;
    int pos = rem % 36;
    int py = pos / 6, px = pos % 6;
    float acc[4][10];
#pragma unroll
    for (int c = 0; c < 10; c++) {
        float bb = s_b[grp * 10 + c];
        acc[0][c] = bb; acc[1][c] = bb; acc[2][c] = bb; acc[3][c] = bb;
    }
    for (int ic = 0; ic < 10; ic++) {
        float p[4][4];
#pragma unroll
        for (int a = 0; a < 4; a++)
#pragma unroll
            for (int b = 0; b < 4; b++)
                p[a][b] = s_in[li][ic][(2 * py + a) * 14 + (2 * px + b)];
#pragma unroll
        for (int c = 0; c < 10; c++) {
            const float* w = &s_w[((grp * 10 + c) * 10 + ic) * 9];
#pragma unroll
            for (int ky = 0; ky < 3; ky++)
#pragma unroll
                for (int kx = 0; kx < 3; kx++) {
                    float wv = w[ky * 3 + kx];
                    acc[0][c] += p[ky][kx] * wv;
                    acc[1][c] += p[ky][kx + 1] * wv;
                    acc[2][c] += p[ky + 1][kx] * wv;
                    acc[3][c] += p[ky + 1][kx + 1] * wv;
                }
        }
    }
    float* out = g_f2 + (size_t)(i0 + li) * 720 + pos;
#pragma unroll
    for (int c = 0; c < 10; c++) {
        float v = fmaxf(fmaxf(fmaxf(acc[0][c], acc[1][c]), fmaxf(acc[2][c], acc[3][c])), 0.f);
        out[(grp * 10 + c) * 36] = v;
    }
}

// ---------------- conv3: (20,6,6) -> (40,3,3), 8 images/block, SCALAR math ----------------
// Structure (smem layout, loads, output mapping) verified numerically in R4's pass;
// inner math is R1's verified scalar form. 288 thr, 69.9KB dyn smem -> 3 blocks/SM.
__global__ __launch_bounds__(288) void k_conv3(const float* __restrict__ w3,
                                               const float* __restrict__ b3) {
    extern __shared__ float sm3[];
    float* s_in = sm3;                 // [8][20][64] zero-padded 8x8 per channel
    float* s_w  = sm3 + 8 * 20 * 64;   // 7200
    float* s_b  = s_w + 7200;          // 40
    int tid = threadIdx.x;
    int i0  = blockIdx.x * 8;
    for (int idx = tid; idx < 8 * 20 * 64; idx += 288) s_in[idx] = 0.f;
    for (int idx = tid; idx < 1800; idx += 288)
        ((float4*)s_w)[idx] = ((const float4*)w3)[idx];
    if (tid < 40) s_b[tid] = b3[tid];
    __syncthreads();
    for (int idx = tid; idx < 8 * 720; idx += 288) {
        int li = idx / 720, r = idx % 720;
        int c = r / 36, rr = r % 36;
        int y = rr / 6, x = rr % 6;
        s_in[(li * 20 + c) * 64 + (y + 1) * 8 + (x + 1)] = g_f2[(size_t)(i0 + li) * 720 + r];
    }
    __syncthreads();
    int li  = tid / 36;
    int rem = tid % 36;
    int grp = rem / 9;
    int pos = rem % 9;
    int py = pos / 3, px = pos % 3;
    float acc[4][10];
#pragma unroll
    for (int c = 0; c < 10; c++) {
        float bb = s_b[grp * 10 + c];
        acc[0][c] = bb; acc[1][c] = bb; acc[2][c] = bb; acc[3][c] = bb;
    }
    for (int ic = 0; ic < 20; ic++) {
        const float* sp = &s_in[(li * 20 + ic) * 64 + (2 * py) * 8 + 2 * px];
        float p[4][4];
#pragma unroll
        for (int a = 0; a < 4; a++)
#pragma unroll
            for (int b = 0; b < 4; b++)
                p[a][b] = sp[a * 8 + b];
#pragma unroll
        for (int c = 0; c < 10; c++) {
            const float* w = &s_w[((grp * 10 + c) * 20 + ic) * 9];
#pragma unroll
            for (int ky = 0; ky < 3; ky++)
#pragma unroll
                for (int kx = 0; kx < 3; kx++) {
                    float wv = w[ky * 3 + kx];
                    acc[0][c] += p[ky][kx] * wv;
                    acc[1][c] += p[ky][kx + 1] * wv;
                    acc[2][c] += p[ky + 1][kx] * wv;
                    acc[3][c] += p[ky + 1][kx + 1] * wv;
                }
        }
    }
    int i = i0 + li;
    int t = i >> 9;      // /512
    int b = i & 511;
#pragma unroll
    for (int c0 = 0; c0 < 10; c0++) {
        int c = grp * 10 + c0;
        int e = c * 9 + pos;        // flatten (40,3,3)
        int r = e / 36, j = e % 36; // view(-1,36)
        float v = fmaxf(fmaxf(fmaxf(acc[0][c0], acc[1][c0]), fmaxf(acc[2][c0], acc[3][c0])), 0.f);
        g_x[((size_t)t * NB + b * 10 + r) * 36 + j] = v;
    }
}

// ---------------- xW precompute (R9 verbatim — measured 506us) ----------------
__global__ __launch_bounds__(256) void k_xw(const float* __restrict__ w_ih,
                                            const float* __restrict__ b_ih,
                                            const float* __restrict__ b_hh) {
    __shared__ float A_s[36 * 132];
    __shared__ float B_s[36 * 68];
    int tid = threadIdx.x;
    long m0 = (long)blockIdx.x * 128;
    int  n0 = blockIdx.y * 64;
    for (int idx = tid; idx < 128 * 36; idx += 256) {
        int mm = idx / 36, k = idx % 36;
        A_s[k * 132 + mm] = g_x[m0 * 36 + idx];
    }
    for (int idx = tid; idx < 64 * 36; idx += 256) {
        int nn = idx / 36, k = idx % 36;
        B_s[k * 68 + nn] = w_ih[(n0 + nn) * 36 + k];
    }
    __syncthreads();
    int cg = tid & 15, rg = tid >> 4;
    float acc[8][4];
#pragma unroll
    for (int i = 0; i < 8; i++)
#pragma unroll
        for (int j = 0; j < 4; j++) acc[i][j] = 0.f;
#pragma unroll
    for (int k = 0; k < 36; k++) {
        float4 a0 = *(const float4*)&A_s[k * 132 + rg * 8];
        float4 a1 = *(const float4*)&A_s[k * 132 + rg * 8 + 4];
        float4 bv = *(const float4*)&B_s[k * 68 + cg * 4];
        float a[8] = {a0.x, a0.y, a0.z, a0.w, a1.x, a1.y, a1.z, a1.w};
        float b[4] = {bv.x, bv.y, bv.z, bv.w};
#pragma unroll
        for (int i = 0; i < 8; i++)
#pragma unroll
            for (int j = 0; j < 4; j++) acc[i][j] += a[i] * b[j];
    }
    float bias[4];
#pragma unroll
    for (int j = 0; j < 4; j++) {
        int col = n0 + cg * 4 + j;
        bias[j] = b_ih[col] + b_hh[col];
    }
#pragma unroll
    for (int i = 0; i < 8; i++) {
        long row = m0 + rg * 8 + i;
        float4 o = make_float4(acc[i][0] + bias[0], acc[i][1] + bias[1],
                               acc[i][2] + bias[2], acc[i][3] + bias[3]);
        *(float4*)&g_G[row * 448 + n0 + cg * 4] = o;
    }
}

// ---------------- LSTM: block-local recurrence (R9 structure; sigm via tanh.approx) ----------------
// block = 40 rows x all 448 gate cols x 64 steps. 256 threads (8 warps x 5 rows).
__global__ __launch_bounds__(LTHR) void k_lstm(const float* __restrict__ w_hh,
                                               const float* __restrict__ h0,
                                               const float* __restrict__ c0,
                                               const float* __restrict__ wf,
                                               const float* __restrict__ bf,
                                               float* __restrict__ out) {
    extern __shared__ float sm[];
    float* wT  = sm;               // [112][448]
    float* h_s = sm + 112 * 448;   // [112][40]  (k-major, stride 40)
    int tid  = threadIdx.x;
    int warp = tid >> 5, lane = tid & 31;
    int r0   = warp * 5;           // 8 warps x 5 rows = 40
    int row0 = blockIdx.x * RROWS;

    // build permuted wT: wT[k][m] = w_hh[n(m)][k], n(m) = (m&3)*112 + (m>>2)
    for (int idx = tid; idx < 448 * 28; idx += LTHR) {
        int n = idx / 28, k4 = (idx % 28) * 4;
        float4 v = *(const float4*)&w_hh[n * 112 + k4];
        int m = ((n % 112) << 2) | (n / 112);
        wT[(k4 + 0) * 448 + m] = v.x;
        wT[(k4 + 1) * 448 + m] = v.y;
        wT[(k4 + 2) * 448 + m] = v.z;
        wT[(k4 + 3) * 448 + m] = v.w;
    }
    // init h: all rows = h0
    for (int idx = tid; idx < 112 * RROWS; idx += LTHR)
        h_s[idx] = h0[idx / RROWS];

    bool evenl = (lane & 1) == 0;
    int  hpair = lane >> 1;
    // cell state: BOTH lanes of a pair keep c for all 7 jj (redundant, removes divergence)
    float c_reg[5][7];
#pragma unroll
    for (int jj = 0; jj < 7; jj++) {
        float cv = c0[hpair + 16 * jj];
#pragma unroll
        for (int r = 0; r < 5; r++) c_reg[r][jj] = cv;
    }
    __syncthreads();

    const float* Gb = g_G + (size_t)row0 * 448;
    int nlo = (evenl ? 0 : 224);   // unpermuted gate-block base for this lane's packed pair
    for (int t = 0; t < T_STEPS; t++) {
        const float* Gt = Gb + (size_t)t * NB * 448;
        unsigned long long acc[5][7];
#pragma unroll
        for (int r = 0; r < 5; r++) {
            const float* gr = Gt + (size_t)(r0 + r) * 448;
#pragma unroll
            for (int jj = 0; jj < 7; jj++) {
                int hc = hpair + 16 * jj;
                float lo = __ldg(&gr[nlo + hc]);          // gate i (even) / g (odd)
                float hi = __ldg(&gr[nlo + 112 + hc]);    // gate f (even) / o (odd)
                PACK2(acc[r][jj], lo, hi);
            }
        }
        // GEMM: acc += h @ wT
#pragma unroll 2
        for (int k = 0; k < 112; k++) {
            unsigned long long ad[5];
#pragma unroll
            for (int r = 0; r < 5; r++) {
                float av = h_s[k * RROWS + r0 + r];
                PACK2(ad[r], av, av);
            }
            const unsigned long long* wp =
                (const unsigned long long*)(wT + k * 448 + 2 * lane);
#pragma unroll
            for (int jj = 0; jj < 7; jj++) {
                unsigned long long bv = wp[32 * jj];
#pragma unroll
                for (int r = 0; r < 5; r++) FFMA2(acc[r][jj], ad[r], bv, acc[r][jj]);
            }
        }
        __syncthreads();   // all GEMM reads of h_s done before overwrite

        // epilogue: exchange with pair lane; both lanes compute the shared cell (no divergence)
#pragma unroll
        for (int r = 0; r < 5; r++) {
#pragma unroll
            for (int jj = 0; jj < 7; jj++) {
                unsigned long long other = __shfl_xor_sync(0xffffffffu, acc[r][jj], 1);
                float x0, x1, y0, y1;
                UNPACK2(x0, x1, acc[r][jj]);
                UNPACK2(y0, y1, other);
                float gi = evenl ? x0 : y0;
                float gf = evenl ? x1 : y1;
                float gg = evenl ? y0 : x0;
                float go = evenl ? y1 : x1;
                float is = sigm_t(gi), fs = sigm_t(gf), os = sigm_t(go);
                float gt = tanh_a(gg);
                float cn = fs * c_reg[r][jj] + is * gt;
                c_reg[r][jj] = cn;
                if (evenl) {
                    int hc = hpair + 16 * jj;
                    h_s[hc * RROWS + r0 + r] = os * tanh_a(cn);
                }
            }
        }
        __syncthreads();
    }

    // head: softmax(h @ wf^T + bf) for this block's 40 rows (reuse wT region as scratch)
    float* lg = wT;   // [40][3]
    if (tid < 120) {
        int r = tid / 3, o = tid % 3;
        float s = bf[o];
        const float* wfo = wf + o * 112;
        for (int k = 0; k < 112; k++) s += h_s[k * RROWS + r] * wfo[k];
        lg[r * 3 + o] = s;
    }
    __syncthreads();
    if (tid < RROWS) {
        float l0 = lg[tid * 3], l1 = lg[tid * 3 + 1], l2 = lg[tid * 3 + 2];
        float mx = fmaxf(l0, fmaxf(l1, l2));
        float e0 = __expf(l0 - mx), e1 = __expf(l1 - mx), e2 = __expf(l2 - mx);
        float s = e0 + e1 + e2;
        int m = row0 + tid;
        out[m * 3 + 0] = e0 / s;
        out[m * 3 + 1] = e1 / s;
        out[m * 3 + 2] = e2 / s;
    }
}

// ---------------- launch ----------------
extern "C" void kernel_launch(void* const* d_in, const int* in_sizes, int n_in,
                              void* d_out, int out_size) {
    const float* imgs = (const float*)d_in[0];
    const float* w1   = (const float*)d_in[1];
    const float* b1   = (const float*)d_in[2];
    const float* w2   = (const float*)d_in[3];
    const float* b2   = (const float*)d_in[4];
    const float* w3   = (const float*)d_in[5];
    const float* b3   = (const float*)d_in[6];
    const float* w_ih = (const float*)d_in[7];
    const float* w_hh = (const float*)d_in[8];
    const float* b_ih = (const float*)d_in[9];
    const float* b_hh = (const float*)d_in[10];
    const float* wf   = (const float*)d_in[11];
    const float* bf   = (const float*)d_in[12];
    const float* h0   = (const float*)d_in[13];
    const float* c0   = (const float*)d_in[14];

    size_t conv3_smem = (size_t)(8 * 20 * 64 + 7200 + 40) * sizeof(float);   // 69,920 B
    size_t lstm_smem  = (size_t)(112 * 448 + 112 * RROWS) * sizeof(float);   // 218,624 B
    cudaFuncSetAttribute(k_conv3, cudaFuncAttributeMaxDynamicSharedMemorySize, (int)(72 * 1024));
    cudaFuncSetAttribute(k_lstm,  cudaFuncAttributeMaxDynamicSharedMemorySize, (int)(220 * 1024));

    k_conv1<<<TB / 2, 288>>>(imgs, w1, b1);
    k_conv2<<<TB / 4, 288>>>(w2, b2);
    k_conv3<<<TB / 8, 288, conv3_smem>>>(w3, b3);
    dim3 gx(2560, 7);
    k_xw<<<gx, 256>>>(w_ih, b_ih, b_hh);
    k_lstm<<<LBLK, LTHR, lstm_smem>>>(w_hh, h0, c0, wf, bf, (float*)d_out);
}

// round 14
// speedup vs baseline: 1.5147x; 1.0346x over previous
#include <cuda_runtime.h>
#include <math.h>

#define TB      32768      // T*B images
#define T_STEPS 64
#define NB      5120       // LSTM batch = B*10
#define HID     112
#define G4      448        // 4*HID
#define RROWS   40         // LSTM rows per block
#define LBLK    128        // NB / RROWS
#define LTHR    256        // 8 warps, 5 rows per warp

// ---------------- scratch (device globals; no runtime allocation) ----------------
__device__ float g_f1[(size_t)TB * 1440];              // (TB,10,12,12)
__device__ float g_f2[(size_t)TB * 720];               // (TB,20,6,6)
__device__ float g_x [(size_t)T_STEPS * NB * 36];      // (T,NB,36)
__device__ float g_G [(size_t)T_STEPS * NB * G4];      // (T,NB,448) NORMAL layout n = gate*112+hc

// ---------------- f32x2 packed-math helpers (LSTM only) ----------------
#define PACK2(d, lo, hi) asm("mov.b64 %0, {%1, %2};" : "=l"(d) : "f"(lo), "f"(hi))
#define UNPACK2(lo, hi, v) asm("mov.b64 {%0, %1}, %2;" : "=f"(lo), "=f"(hi) : "l"(v))
#define FFMA2(d, a, b, c) asm("fma.rn.f32x2 %0, %1, %2, %3;" : "=l"(d) : "l"(a), "l"(b), "l"(c))

__device__ __forceinline__ float tanh_a(float x) {
    float y;
    asm("tanh.approx.f32 %0, %1;" : "=f"(y) : "f"(x));
    return y;
}
// sigmoid via tanh: 1 MUFU instead of 2 (EX2 + RCP)
__device__ __forceinline__ float sigm_t(float x) { return 0.5f * tanh_a(0.5f * x) + 0.5f; }

// ---------------- conv1: (1,24,24) -> conv3x3 SAME + relu + pool2 -> (10,12,12) ----------------
// (R1 verbatim — measured passing)
__global__ __launch_bounds__(288) void k_conv1(const float* __restrict__ imgs,
                                               const float* __restrict__ w1,
                                               const float* __restrict__ b1) {
    __shared__ float s_img[2][26 * 26];
    __shared__ float s_w[90];
    __shared__ float s_b[10];
    int tid = threadIdx.x;
    int i0  = blockIdx.x * 2;
    for (int idx = tid; idx < 2 * 676; idx += 288) ((float*)s_img)[idx] = 0.f;
    if (tid < 90) s_w[tid] = w1[tid];
    if (tid < 10) s_b[tid] = b1[tid];
    __syncthreads();
    for (int idx = tid; idx < 2 * 576; idx += 288) {
        int li = idx / 576, r = idx % 576;
        int y = r / 24, x = r % 24;
        s_img[li][(y + 1) * 26 + (x + 1)] = imgs[(size_t)(i0 + li) * 576 + r];
    }
    __syncthreads();
    int li  = tid / 144;
    int pos = tid % 144;
    int py = pos / 12, px = pos % 12;
    float p[4][4];
#pragma unroll
    for (int a = 0; a < 4; a++)
#pragma unroll
        for (int b = 0; b < 4; b++)
            p[a][b] = s_img[li][(2 * py + a) * 26 + (2 * px + b)];
    float* out = g_f1 + (size_t)(i0 + li) * 1440 + pos;
#pragma unroll
    for (int c = 0; c < 10; c++) {
        float bb = s_b[c];
        float a00 = bb, a01 = bb, a10 = bb, a11 = bb;
#pragma unroll
        for (int ky = 0; ky < 3; ky++)
#pragma unroll
            for (int kx = 0; kx < 3; kx++) {
                float w = s_w[c * 9 + ky * 3 + kx];
                a00 += p[ky][kx] * w;
                a01 += p[ky][kx + 1] * w;
                a10 += p[ky + 1][kx] * w;
                a11 += p[ky + 1][kx + 1] * w;
            }
        out[c * 144] = fmaxf(fmaxf(fmaxf(a00, a01), fmaxf(a10, a11)), 0.f);
    }
}

// ---------------- conv2: (10,12,12) -> (20,6,6) (R1 verbatim — measured passing) ----------------
__global__ __launch_bounds__(288) void k_conv2(const float* __restrict__ w2,
                                               const float* __restrict__ b2) {
    __shared__ float s_in[4][10][14 * 14];
    __shared__ float s_w[1800];
    __shared__ float s_b[20];
    int tid = threadIdx.x;
    int i0  = blockIdx.x * 4;
    for (int idx = tid; idx < 4 * 10 * 196; idx += 288) ((float*)s_in)[idx] = 0.f;
    for (int idx = tid; idx < 1800; idx += 288) s_w[idx] = w2[idx];
    if (tid < 20) s_b[tid] = b2[tid];
    __syncthreads();
    for (int idx = tid; idx < 4 * 1440; idx += 288) {
        int li = idx / 1440, r = idx % 1440;
        int c = r / 144, rr = r % 144;
        int y = rr / 12, x = rr % 12;
        s_in[li][c][(y + 1) * 14 + (x + 1)] = g_f1[(size_t)(i0 + li) * 1440 + r];
    }
    __syncthreads();
    int li  = tid / 72;
    int rem = tid % 72;
    int grp = rem / 36;
    int pos = rem % 36;
    int py = pos / 6, px = pos % 6;
    float acc[4][10];
#pragma unroll
    for (int c = 0; c < 10; c++) {
        float bb = s_b[grp * 10 + c];
        acc[0][c] = bb; acc[1][c] = bb; acc[2][c] = bb; acc[3][c] = bb;
    }
    for (int ic = 0; ic < 10; ic++) {
        float p[4][4];
#pragma unroll
        for (int a = 0; a < 4; a++)
#pragma unroll
            for (int b = 0; b < 4; b++)
                p[a][b] = s_in[li][ic][(2 * py + a) * 14 + (2 * px + b)];
#pragma unroll
        for (int c = 0; c < 10; c++) {
            const float* w = &s_w[((grp * 10 + c) * 10 + ic) * 9];
#pragma unroll
            for (int ky = 0; ky < 3; ky++)
#pragma unroll
                for (int kx = 0; kx < 3; kx++) {
                    float wv = w[ky * 3 + kx];
                    acc[0][c] += p[ky][kx] * wv;
                    acc[1][c] += p[ky][kx + 1] * wv;
                    acc[2][c] += p[ky + 1][kx] * wv;
                    acc[3][c] += p[ky + 1][kx + 1] * wv;
                }
        }
    }
    float* out = g_f2 + (size_t)(i0 + li) * 720 + pos;
#pragma unroll
    for (int c = 0; c < 10; c++) {
        float v = fmaxf(fmaxf(fmaxf(acc[0][c], acc[1][c]), fmaxf(acc[2][c], acc[3][c])), 0.f);
        out[(grp * 10 + c) * 36] = v;
    }
}

// ---------------- conv3: (20,6,6) -> (40,3,3), 8 images/block, SCALAR math (R13 verbatim — WIN) ----------------
__global__ __launch_bounds__(288) void k_conv3(const float* __restrict__ w3,
                                               const float* __restrict__ b3) {
    extern __shared__ float sm3[];
    float* s_in = sm3;                 // [8][20][64] zero-padded 8x8 per channel
    float* s_w  = sm3 + 8 * 20 * 64;   // 7200
    float* s_b  = s_w + 7200;          // 40
    int tid = threadIdx.x;
    int i0  = blockIdx.x * 8;
    for (int idx = tid; idx < 8 * 20 * 64; idx += 288) s_in[idx] = 0.f;
    for (int idx = tid; idx < 1800; idx += 288)
        ((float4*)s_w)[idx] = ((const float4*)w3)[idx];
    if (tid < 40) s_b[tid] = b3[tid];
    __syncthreads();
    for (int idx = tid; idx < 8 * 720; idx += 288) {
        int li = idx / 720, r = idx % 720;
        int c = r / 36, rr = r % 36;
        int y = rr / 6, x = rr % 6;
        s_in[(li * 20 + c) * 64 + (y + 1) * 8 + (x + 1)] = g_f2[(size_t)(i0 + li) * 720 + r];
    }
    __syncthreads();
    int li  = tid / 36;
    int rem = tid % 36;
    int grp = rem / 9;
    int pos = rem % 9;
    int py = pos / 3, px = pos % 3;
    float acc[4][10];
#pragma unroll
    for (int c = 0; c < 10; c++) {
        float bb = s_b[grp * 10 + c];
        acc[0][c] = bb; acc[1][c] = bb; acc[2][c] = bb; acc[3][c] = bb;
    }
    for (int ic = 0; ic < 20; ic++) {
        const float* sp = &s_in[(li * 20 + ic) * 64 + (2 * py) * 8 + 2 * px];
        float p[4][4];
#pragma unroll
        for (int a = 0; a < 4; a++)
#pragma unroll
            for (int b = 0; b < 4; b++)
                p[a][b] = sp[a * 8 + b];
#pragma unroll
        for (int c = 0; c < 10; c++) {
            const float* w = &s_w[((grp * 10 + c) * 20 + ic) * 9];
#pragma unroll
            for (int ky = 0; ky < 3; ky++)
#pragma unroll
                for (int kx = 0; kx < 3; kx++) {
                    float wv = w[ky * 3 + kx];
                    acc[0][c] += p[ky][kx] * wv;
                    acc[1][c] += p[ky][kx + 1] * wv;
                    acc[2][c] += p[ky + 1][kx] * wv;
                    acc[3][c] += p[ky + 1][kx + 1] * wv;
                }
        }
    }
    int i = i0 + li;
    int t = i >> 9;      // /512
    int b = i & 511;
#pragma unroll
    for (int c0 = 0; c0 < 10; c0++) {
        int c = grp * 10 + c0;
        int e = c * 9 + pos;        // flatten (40,3,3)
        int r = e / 36, j = e % 36; // view(-1,36)
        float v = fmaxf(fmaxf(fmaxf(acc[0][c0], acc[1][c0]), fmaxf(acc[2][c0], acc[3][c0])), 0.f);
        g_x[((size_t)t * NB + b * 10 + r) * 36 + j] = v;
    }
}

// ---------------- xW precompute: 64x64 tile, 4x4/thread — higher occupancy, shorter dep chains ----------------
// grid (5120, 7), 256 threads. acc 16 regs (vs 32) -> ~5 blocks/SM vs 4.
__global__ __launch_bounds__(256) void k_xw(const float* __restrict__ w_ih,
                                            const float* __restrict__ b_ih,
                                            const float* __restrict__ b_hh) {
    __shared__ float A_s[36 * 68];   // x tile, K-major, padded stride
    __shared__ float B_s[36 * 68];   // w_ih tile, K-major
    int tid = threadIdx.x;
    long m0 = (long)blockIdx.x * 64;
    int  n0 = blockIdx.y * 64;
    for (int idx = tid; idx < 64 * 36; idx += 256) {
        int mm = idx / 36, k = idx % 36;
        A_s[k * 68 + mm] = g_x[m0 * 36 + idx];
    }
    for (int idx = tid; idx < 64 * 36; idx += 256) {
        int nn = idx / 36, k = idx % 36;
        B_s[k * 68 + nn] = w_ih[(n0 + nn) * 36 + k];
    }
    __syncthreads();
    int cg = tid & 15, rg = tid >> 4;
    float acc[4][4];
#pragma unroll
    for (int i = 0; i < 4; i++)
#pragma unroll
        for (int j = 0; j < 4; j++) acc[i][j] = 0.f;
#pragma unroll
    for (int k = 0; k < 36; k++) {
        float4 av = *(const float4*)&A_s[k * 68 + rg * 4];
        float4 bv = *(const float4*)&B_s[k * 68 + cg * 4];
        float a[4] = {av.x, av.y, av.z, av.w};
        float b[4] = {bv.x, bv.y, bv.z, bv.w};
#pragma unroll
        for (int i = 0; i < 4; i++)
#pragma unroll
            for (int j = 0; j < 4; j++) acc[i][j] += a[i] * b[j];
    }
    float bias[4];
#pragma unroll
    for (int j = 0; j < 4; j++) {
        int col = n0 + cg * 4 + j;
        bias[j] = b_ih[col] + b_hh[col];
    }
#pragma unroll
    for (int i = 0; i < 4; i++) {
        long row = m0 + rg * 4 + i;
        float4 o = make_float4(acc[i][0] + bias[0], acc[i][1] + bias[1],
                               acc[i][2] + bias[2], acc[i][3] + bias[3]);
        *(float4*)&g_G[row * 448 + n0 + cg * 4] = o;
    }
}

// ---------------- LSTM: block-local recurrence; epilogue lane-split (even jj0-3, odd jj4-6) ----------------
// block = 40 rows x all 448 gate cols x 64 steps. 256 threads (8 warps x 5 rows).
__global__ __launch_bounds__(LTHR) void k_lstm(const float* __restrict__ w_hh,
                                               const float* __restrict__ h0,
                                               const float* __restrict__ c0,
                                               const float* __restrict__ wf,
                                               const float* __restrict__ bf,
                                               float* __restrict__ out) {
    extern __shared__ float sm[];
    float* wT  = sm;               // [112][448]
    float* h_s = sm + 112 * 448;   // [112][40]  (k-major, stride 40)
    int tid  = threadIdx.x;
    int warp = tid >> 5, lane = tid & 31;
    int r0   = warp * 5;           // 8 warps x 5 rows = 40
    int row0 = blockIdx.x * RROWS;

    // build permuted wT: wT[k][m] = w_hh[n(m)][k], n(m) = (m&3)*112 + (m>>2)
    for (int idx = tid; idx < 448 * 28; idx += LTHR) {
        int n = idx / 28, k4 = (idx % 28) * 4;
        float4 v = *(const float4*)&w_hh[n * 112 + k4];
        int m = ((n % 112) << 2) | (n / 112);
        wT[(k4 + 0) * 448 + m] = v.x;
        wT[(k4 + 1) * 448 + m] = v.y;
        wT[(k4 + 2) * 448 + m] = v.z;
        wT[(k4 + 3) * 448 + m] = v.w;
    }
    // init h: all rows = h0
    for (int idx = tid; idx < 112 * RROWS; idx += LTHR)
        h_s[idx] = h0[idx / RROWS];

    bool evenl = (lane & 1) == 0;
    int  hpair = lane >> 1;
    // cell state: even lane owns cells jj 0..3, odd lane jj 4..6 (slot q)
    float c_reg[5][4];
#pragma unroll
    for (int q = 0; q < 4; q++) {
        int jj = evenl ? q : (q < 3 ? 4 + q : 6);
        float cv = c0[hpair + 16 * jj];
#pragma unroll
        for (int r = 0; r < 5; r++) c_reg[r][q] = cv;
    }
    __syncthreads();

    const float* Gb = g_G + (size_t)row0 * 448;
    int nlo = (evenl ? 0 : 224);   // unpermuted gate-block base for this lane's packed pair
    for (int t = 0; t < T_STEPS; t++) {
        const float* Gt = Gb + (size_t)t * NB * 448;
        unsigned long long acc[5][7];
#pragma unroll
        for (int r = 0; r < 5; r++) {
            const float* gr = Gt + (size_t)(r0 + r) * 448;
#pragma unroll
            for (int jj = 0; jj < 7; jj++) {
                int hc = hpair + 16 * jj;
                float lo = __ldg(&gr[nlo + hc]);          // gate i (even) / g (odd)
                float hi = __ldg(&gr[nlo + 112 + hc]);    // gate f (even) / o (odd)
                PACK2(acc[r][jj], lo, hi);
            }
        }
        // GEMM: acc += h @ wT
#pragma unroll 2
        for (int k = 0; k < 112; k++) {
            unsigned long long ad[5];
#pragma unroll
            for (int r = 0; r < 5; r++) {
                float av = h_s[k * RROWS + r0 + r];
                PACK2(ad[r], av, av);
            }
            const unsigned long long* wp =
                (const unsigned long long*)(wT + k * 448 + 2 * lane);
#pragma unroll
            for (int jj = 0; jj < 7; jj++) {
                unsigned long long bv = wp[32 * jj];
#pragma unroll
                for (int r = 0; r < 5; r++) FFMA2(acc[r][jj], ad[r], bv, acc[r][jj]);
            }
        }
        __syncthreads();   // all GEMM reads of h_s done before overwrite

        // epilogue: lane-split — even lane computes cells jj=q (0..3), odd lane jj=4+q (q<3).
        // shfl provides the PARTNER's accumulator for the partner's cell:
        //   even provides acc[4+q] (odd needs it), odd provides acc[q] (even needs it).
#pragma unroll
        for (int r = 0; r < 5; r++) {
#pragma unroll
            for (int q = 0; q < 4; q++) {
                int provide_jj = evenl ? (q < 3 ? 4 + q : 6) : q;
                unsigned long long other = __shfl_xor_sync(0xffffffffu, acc[r][provide_jj], 1);
                if (evenl || q < 3) {
                    int jj = evenl ? q : 4 + q;
                    float x0, x1, y0, y1;
                    UNPACK2(x0, x1, acc[r][jj]);   // own pair for this cell
                    UNPACK2(y0, y1, other);        // partner's pair for this cell
                    float gi = evenl ? x0 : y0;
                    float gf = evenl ? x1 : y1;
                    float gg = evenl ? y0 : x0;
                    float go = evenl ? y1 : x1;
                    float is = sigm_t(gi), fs = sigm_t(gf), os = sigm_t(go);
                    float gt = tanh_a(gg);
                    float cn = fs * c_reg[r][q] + is * gt;
                    c_reg[r][q] = cn;
                    int hc = hpair + 16 * jj;
                    h_s[hc * RROWS + r0 + r] = os * tanh_a(cn);
                }
            }
        }
        __syncthreads();
    }

    // head: softmax(h @ wf^T + bf) for this block's 40 rows (reuse wT region as scratch)
    float* lg = wT;   // [40][3]
    if (tid < 120) {
        int r = tid / 3, o = tid % 3;
        float s = bf[o];
        const float* wfo = wf + o * 112;
        for (int k = 0; k < 112; k++) s += h_s[k * RROWS + r] * wfo[k];
        lg[r * 3 + o] = s;
    }
    __syncthreads();
    if (tid < RROWS) {
        float l0 = lg[tid * 3], l1 = lg[tid * 3 + 1], l2 = lg[tid * 3 + 2];
        float mx = fmaxf(l0, fmaxf(l1, l2));
        float e0 = __expf(l0 - mx), e1 = __expf(l1 - mx), e2 = __expf(l2 - mx);
        float s = e0 + e1 + e2;
        int m = row0 + tid;
        out[m * 3 + 0] = e0 / s;
        out[m * 3 + 1] = e1 / s;
        out[m * 3 + 2] = e2 / s;
    }
}

// ---------------- launch ----------------
extern "C" void kernel_launch(void* const* d_in, const int* in_sizes, int n_in,
                              void* d_out, int out_size) {
    const float* imgs = (const float*)d_in[0];
    const float* w1   = (const float*)d_in[1];
    const float* b1   = (const float*)d_in[2];
    const float* w2   = (const float*)d_in[3];
    const float* b2   = (const float*)d_in[4];
    const float* w3   = (const float*)d_in[5];
    const float* b3   = (const float*)d_in[6];
    const float* w_ih = (const float*)d_in[7];
    const float* w_hh = (const float*)d_in[8];
    const float* b_ih = (const float*)d_in[9];
    const float* b_hh = (const float*)d_in[10];
    const float* wf   = (const float*)d_in[11];
    const float* bf   = (const float*)d_in[12];
    const float* h0   = (const float*)d_in[13];
    const float* c0   = (const float*)d_in[14];

    size_t conv3_smem = (size_t)(8 * 20 * 64 + 7200 + 40) * sizeof(float);   // 69,920 B
    size_t lstm_smem  = (size_t)(112 * 448 + 112 * RROWS) * sizeof(float);   // 218,624 B
    cudaFuncSetAttribute(k_conv3, cudaFuncAttributeMaxDynamicSharedMemorySize, (int)(72 * 1024));
    cudaFuncSetAttribute(k_lstm,  cudaFuncAttributeMaxDynamicSharedMemorySize, (int)(220 * 1024));

    k_conv1<<<TB / 2, 288>>>(imgs, w1, b1);
    k_conv2<<<TB / 4, 288>>>(w2, b2);
    k_conv3<<<TB / 8, 288, conv3_smem>>>(w3, b3);
    dim3 gx(5120, 7);
    k_xw<<<gx, 256>>>(w_ih, b_ih, b_hh);
    k_lstm<<<LBLK, LTHR, lstm_smem>>>(w_hh, h0, c0, wf, bf, (float*)d_out);
}